// round 10
// baseline (speedup 1.0000x reference)
#include <cuda_runtime.h>
#include <math_constants.h>

// FusedScaleMaskSoftmax: x[2,16,2048,2048] fp32 -> causal-masked softmax (last dim).
//
// R9: heterogeneous single-launch grid. R8's two-phase split showed the traffic
// floor (768MB) is fully bandwidth-bound at the chip's ~6.4TB/s LTS cap, but
// lost ~4us to inter-kernel serialization (B waits for ALL of A). Here both
// phases live in ONE grid: even blockIdx -> zero-fill CTA (pure-write warps
// covering all fully-masked 32B chunks), odd blockIdx -> softmax CTA (causal
// prefix: 256-bit loads, exp2, warp-shuffle sum, 256-bit stores). Chunk sets
// are disjoint -> no ordering needed; interleaved bids keep the global R/W mix
// constant in time and the scheduler fills SMs with no phase barrier.
// Balanced row pairing (j <-> 2047-j) keeps per-warp-pair work constant.

#define SK        2048
#define THREADS   256            // 8 warps = 8 rows per CTA (per type)
#define WARPS_PB  (THREADS / 32)
#define NC        8              // 256-bit chunks per lane (softmax CTAs)
#define NCHUNKS   (SK / 8)       // 256 chunks per row

__device__ __forceinline__ float ex2_approx(float x) {
    float r;
    asm("ex2.approx.ftz.f32 %0, %1;" : "=f"(r) : "f"(x));
    return r;
}

__device__ __forceinline__ void ldg256_cs(const float* p, float* v) {
    unsigned u0, u1, u2, u3, u4, u5, u6, u7;
    asm volatile("ld.global.cs.v8.b32 {%0,%1,%2,%3,%4,%5,%6,%7}, [%8];"
        : "=r"(u0), "=r"(u1), "=r"(u2), "=r"(u3),
          "=r"(u4), "=r"(u5), "=r"(u6), "=r"(u7)
        : "l"(p));
    v[0] = __uint_as_float(u0); v[1] = __uint_as_float(u1);
    v[2] = __uint_as_float(u2); v[3] = __uint_as_float(u3);
    v[4] = __uint_as_float(u4); v[5] = __uint_as_float(u5);
    v[6] = __uint_as_float(u6); v[7] = __uint_as_float(u7);
}

__device__ __forceinline__ void stg256(float* p, const float* v) {
    asm volatile("st.global.v8.b32 [%0], {%1,%2,%3,%4,%5,%6,%7,%8};"
        :: "l"(p),
           "r"(__float_as_uint(v[0])), "r"(__float_as_uint(v[1])),
           "r"(__float_as_uint(v[2])), "r"(__float_as_uint(v[3])),
           "r"(__float_as_uint(v[4])), "r"(__float_as_uint(v[5])),
           "r"(__float_as_uint(v[6])), "r"(__float_as_uint(v[7]))
        : "memory");
}

// Balanced row mapping: pair j with 2047-j within each 2048-row matrix.
__device__ __forceinline__ unsigned map_row(unsigned g) {
    const unsigned q = g & (SK - 1);
    const unsigned j = q >> 1;
    const unsigned r = (q & 1u) ? (SK - 1 - j) : j;
    return (g & ~(unsigned)(SK - 1)) | r;
}

__global__ __launch_bounds__(THREADS)
void fused_causal_softmax_hetero(const float* __restrict__ x,
                                 float* __restrict__ out) {
    const float C = 0.08838834764831845f * 1.4426950408889634f;  // SCALE*log2(e)

    const int wid = threadIdx.x >> 5;
    const int lid = threadIdx.x & 31;

    const unsigned bid  = blockIdx.x;
    const unsigned sub  = bid >> 1;                  // index within type, 0..8191
    const unsigned g    = sub * WARPS_PB + wid;      // per-type global warp id
    const unsigned row  = map_row(g);
    const int L = (int)(row & (SK - 1)) + 1;         // valid prefix length

    const size_t base_elem = (size_t)row * SK;
    float* __restrict__ yrow = out + base_elem;

    if ((bid & 1u) == 0u) {
        // ---------------- Zero-fill CTA: pure-write warps ----------------
        const int c0 = (L + 7) >> 3;                 // first fully-masked chunk
        const float z[8] = {0.f, 0.f, 0.f, 0.f, 0.f, 0.f, 0.f, 0.f};
        for (int c = c0 + lid; c < NCHUNKS; c += 32)
            stg256(yrow + (c << 3), z);
        return;
    }

    // ---------------- Softmax CTA: causal prefix only ----------------
    const float* __restrict__ xrow = x + base_elem;

    float v[NC][8];

    // Front-batched 256-bit loads of valid chunks (8c < L).
    #pragma unroll
    for (int k = 0; k < NC; k++) {
        const int b = (lid + k * 32) << 3;
        if (b < L) ldg256_cs(xrow + b, v[k]);
    }

    // exp2(x*C), per-lane tail mask -> exact 0 in the partial chunk.
    float s = 0.0f;
    #pragma unroll
    for (int k = 0; k < NC; k++) {
        const int b = (lid + k * 32) << 3;
        if (b < L) {
            float a[8];
            #pragma unroll
            for (int e = 0; e < 8; e++)
                a[e] = (b + e < L) ? ex2_approx(v[k][e] * C) : 0.0f;
            #pragma unroll
            for (int e = 0; e < 8; e++)
                v[k][e] = a[e];
            s += ((a[0] + a[1]) + (a[2] + a[3]))
               + ((a[4] + a[5]) + (a[6] + a[7]));
        }
    }

    // Warp sum-reduce (no barriers).
    #pragma unroll
    for (int o = 16; o > 0; o >>= 1)
        s += __shfl_xor_sync(0xffffffffu, s, o);

    float inv;
    asm("rcp.approx.ftz.f32 %0, %1;" : "=f"(inv) : "f"(s));

    // Normalize + 256-bit store of valid chunks only.
    #pragma unroll
    for (int k = 0; k < NC; k++) {
        const int b = (lid + k * 32) << 3;
        if (b < L) {
            float o[8];
            #pragma unroll
            for (int e = 0; e < 8; e++)
                o[e] = v[k][e] * inv;
            stg256(yrow + b, o);
        }
    }
}

extern "C" void kernel_launch(void* const* d_in, const int* in_sizes, int n_in,
                              void* d_out, int out_size) {
    const float* x = (const float*)d_in[0];
    float* out = (float*)d_out;

    const int rows   = out_size / SK;              // 65536
    const int blocks = 2 * (rows / WARPS_PB);      // 16384 (half zero, half softmax)
    fused_causal_softmax_hetero<<<blocks, THREADS>>>(x, out);
}

// round 11
// speedup vs baseline: 1.0281x; 1.0281x over previous
#include <cuda_runtime.h>
#include <math_constants.h>

// FusedScaleMaskSoftmax: x[2,16,2048,2048] fp32 -> causal-masked softmax (last dim).
//
// R10: R8's two-phase split (best wall: 120.9us) + PDL overlap.
//   Kernel A: pure-write zero-fill of all fully-masked 32B chunks (256MB).
//   Kernel B: softmax over the causal prefix (256MB read + 256MB write).
// A and B touch DISJOINT output chunks and have no data dependency, yet plain
// stream order forces B to wait for A's last CTA (~4us dead ramp measured as
// wall - sum(ncu durs)). PDL removes that: A triggers programmatic completion
// at entry; B is launched with programmaticStreamSerializationAllowed so its
// CTAs come up while A drains. B never calls cudaGridDependencySynchronize
// (nothing to wait for). If the runtime serializes anyway, behavior == R8.

#define SK        2048
#define THREADS   256            // 8 warps = 8 rows per block
#define WARPS_PB  (THREADS / 32)
#define NC        8              // 256-bit chunks per lane in kernel B
#define NCHUNKS   (SK / 8)       // 256 chunks per row

__device__ __forceinline__ float ex2_approx(float x) {
    float r;
    asm("ex2.approx.ftz.f32 %0, %1;" : "=f"(r) : "f"(x));
    return r;
}

__device__ __forceinline__ void ldg256_cs(const float* p, float* v) {
    unsigned u0, u1, u2, u3, u4, u5, u6, u7;
    asm volatile("ld.global.cs.v8.b32 {%0,%1,%2,%3,%4,%5,%6,%7}, [%8];"
        : "=r"(u0), "=r"(u1), "=r"(u2), "=r"(u3),
          "=r"(u4), "=r"(u5), "=r"(u6), "=r"(u7)
        : "l"(p));
    v[0] = __uint_as_float(u0); v[1] = __uint_as_float(u1);
    v[2] = __uint_as_float(u2); v[3] = __uint_as_float(u3);
    v[4] = __uint_as_float(u4); v[5] = __uint_as_float(u5);
    v[6] = __uint_as_float(u6); v[7] = __uint_as_float(u7);
}

__device__ __forceinline__ void stg256(float* p, const float* v) {
    asm volatile("st.global.v8.b32 [%0], {%1,%2,%3,%4,%5,%6,%7,%8};"
        :: "l"(p),
           "r"(__float_as_uint(v[0])), "r"(__float_as_uint(v[1])),
           "r"(__float_as_uint(v[2])), "r"(__float_as_uint(v[3])),
           "r"(__float_as_uint(v[4])), "r"(__float_as_uint(v[5])),
           "r"(__float_as_uint(v[6])), "r"(__float_as_uint(v[7]))
        : "memory");
}

// Balanced row mapping: pair j with 2047-j within each 2048-row matrix.
__device__ __forceinline__ unsigned map_row(unsigned g) {
    const unsigned q = g & (SK - 1);
    const unsigned j = q >> 1;
    const unsigned r = (q & 1u) ? (SK - 1 - j) : j;
    return (g & ~(unsigned)(SK - 1)) | r;
}

// ---------------- Kernel A: pure-write zero-fill of masked chunks ----------------
__global__ __launch_bounds__(THREADS)
void causal_zero_tail(float* __restrict__ out) {
    // Nothing downstream depends on A's output ordering: release the
    // programmatic-launch gate immediately so B's CTAs can start while A runs.
    cudaTriggerProgrammaticLaunchCompletion();

    const int wid = threadIdx.x >> 5;
    const int lid = threadIdx.x & 31;

    const unsigned g   = blockIdx.x * WARPS_PB + wid;
    const unsigned row = map_row(g);
    const int L  = (int)(row & (SK - 1)) + 1;
    const int c0 = (L + 7) >> 3;          // first fully-masked chunk

    float* __restrict__ yrow = out + (size_t)row * SK;
    const float z[8] = {0.f, 0.f, 0.f, 0.f, 0.f, 0.f, 0.f, 0.f};

    // Consecutive lanes write consecutive 32B chunks -> 1KB per warp instr.
    for (int c = c0 + lid; c < NCHUNKS; c += 32)
        stg256(yrow + (c << 3), z);
}

// ---------------- Kernel B: softmax over the causal prefix ----------------
__global__ __launch_bounds__(THREADS)
void causal_softmax_prefix(const float* __restrict__ x,
                           float* __restrict__ out) {
    // SCALE * log2(e): fold 1/sqrt(128) into the exp2 argument.
    const float C = 0.08838834764831845f * 1.4426950408889634f;

    const int wid = threadIdx.x >> 5;
    const int lid = threadIdx.x & 31;

    const unsigned g   = blockIdx.x * WARPS_PB + wid;
    const unsigned row = map_row(g);
    const int L = (int)(row & (SK - 1)) + 1;

    const size_t base_elem = (size_t)row * SK;
    const float* __restrict__ xrow = x   + base_elem;
    float* __restrict__       yrow = out + base_elem;

    float v[NC][8];

    // Front-batched 256-bit loads of valid chunks (8c < L).
    #pragma unroll
    for (int k = 0; k < NC; k++) {
        const int b = (lid + k * 32) << 3;
        if (b < L) ldg256_cs(xrow + b, v[k]);
    }

    // exp2(x*C) with per-element tail mask (partial chunk lanes -> exact 0).
    float s = 0.0f;
    #pragma unroll
    for (int k = 0; k < NC; k++) {
        const int b = (lid + k * 32) << 3;
        if (b < L) {
            float a[8];
            #pragma unroll
            for (int e = 0; e < 8; e++)
                a[e] = (b + e < L) ? ex2_approx(v[k][e] * C) : 0.0f;
            #pragma unroll
            for (int e = 0; e < 8; e++)
                v[k][e] = a[e];
            s += ((a[0] + a[1]) + (a[2] + a[3]))
               + ((a[4] + a[5]) + (a[6] + a[7]));
        }
    }

    // Warp sum-reduce (no barriers).
    #pragma unroll
    for (int o = 16; o > 0; o >>= 1)
        s += __shfl_xor_sync(0xffffffffu, s, o);

    float inv;
    asm("rcp.approx.ftz.f32 %0, %1;" : "=f"(inv) : "f"(s));

    // Normalize + 256-bit store of valid chunks only.
    #pragma unroll
    for (int k = 0; k < NC; k++) {
        const int b = (lid + k * 32) << 3;
        if (b < L) {
            float o[8];
            #pragma unroll
            for (int e = 0; e < 8; e++)
                o[e] = v[k][e] * inv;
            stg256(yrow + b, o);
        }
    }
}

extern "C" void kernel_launch(void* const* d_in, const int* in_sizes, int n_in,
                              void* d_out, int out_size) {
    const float* x = (const float*)d_in[0];
    float* out = (float*)d_out;

    const int rows   = out_size / SK;          // 65536
    const int blocks = rows / WARPS_PB;        // 8192

    // Phase 1: pure-write burst (masked chunks). Triggers PDL gate at entry.
    causal_zero_tail<<<blocks, THREADS>>>(out);

    // Phase 2: softmax over valid prefix, launched with programmatic stream
    // serialization so its CTAs may start before kernel A fully retires
    // (disjoint chunk sets -> no dependency; B never grid-syncs).
    cudaLaunchAttribute attrs[1];
    attrs[0].id = cudaLaunchAttributeProgrammaticStreamSerialization;
    attrs[0].val.programmaticStreamSerializationAllowed = 1;

    cudaLaunchConfig_t cfg = {};
    cfg.gridDim  = dim3(blocks, 1, 1);
    cfg.blockDim = dim3(THREADS, 1, 1);
    cfg.dynamicSmemBytes = 0;
    cfg.stream = 0;                 // same (capture) stream as kernel A
    cfg.attrs = attrs;
    cfg.numAttrs = 1;

    cudaLaunchKernelEx(&cfg, causal_softmax_prefix, x, out);
}